// round 12
// baseline (speedup 1.0000x reference)
#include <cuda_runtime.h>
#include <cuda_bf16.h>
#include <cuda_pipeline.h>

#define D_MODEL   1024
#define MAX_SEGS  256
#define NTHREADS  256
#define NBLOCKS   1184       // measured-optimal grid region
#define TILE      8

__device__ float g_seg_sum[MAX_SEGS];              // zero-init at load; norm re-zeroes
__device__ float g_scratch[MAX_SEGS * D_MODEL];    // zero-init at load; norm re-zeroes

// ---------------------------------------------------------------------------
// Pool kernel: CTA-per-token-range, 8-token tiles, cp.async double-buffered
// into dynamic smem. Thread tid owns column [4*tid, 4*tid+4): it copies and
// consumes ONLY buf[j][tid] -> no cross-thread hazards on the buffers.
// Prefetch depth lives in smem (2 x 32KB), not registers -> ~96KB/SM in
// flight at 3 CTAs/SM while regs stay ~45.
// ---------------------------------------------------------------------------
extern __shared__ float4 dynbuf[];   // [2][TILE][256]

__global__ __launch_bounds__(NTHREADS)
void pool_kernel(const float* __restrict__ x,
                 const int*   __restrict__ cu,
                 const float* __restrict__ Wp,
                 const float* __restrict__ bp,
                 int T, int nseg) {
    __shared__ float s_part[8][TILE];   // [warp][token]
    __shared__ float s_p[TILE];
    __shared__ int   s_cu[MAX_SEGS + 1];

    const int tid  = threadIdx.x;
    const int lane = tid & 31;
    const int wid  = tid >> 5;

    if (tid <= nseg) s_cu[tid] = cu[tid];

    const float4 w = *reinterpret_cast<const float4*>(Wp + tid * 4);
    const float  b = bp[0];

    const int per = (T + NBLOCKS - 1) / NBLOCKS;   // 111 for T=131072
    const int t0  = blockIdx.x * per;
    const int t1  = min(t0 + per, T);
    __syncthreads();
    if (t0 >= t1) return;

    int seg = 0;
    while (s_cu[seg + 1] <= t0) seg++;
    int nb = s_cu[seg + 1];

    float4 acc = make_float4(0.f, 0.f, 0.f, 0.f);
    float  sump = 0.0f;
    const float4* xv = reinterpret_cast<const float4*>(x);

    float4* const buf0 = dynbuf;
    float4* const buf1 = dynbuf + TILE * 256;

#define PREF(tt, nval, buf)                                                \
    do {                                                                   \
        _Pragma("unroll")                                                  \
        for (int j = 0; j < TILE; j++)                                     \
            if (j < (nval))                                                \
                __pipeline_memcpy_async(&(buf)[j * 256 + tid],             \
                                        &xv[(size_t)((tt) + j) * 256 + tid], 16); \
        __pipeline_commit();                                               \
    } while (0)

#define FLUSH()                                                            \
    do {                                                                   \
        float* o = g_scratch + (size_t)seg * D_MODEL + tid * 4;            \
        atomicAdd(o + 0, acc.x);  atomicAdd(o + 1, acc.y);                 \
        atomicAdd(o + 2, acc.z);  atomicAdd(o + 3, acc.w);                 \
        if (tid == 0) atomicAdd(&g_seg_sum[seg], sump);                    \
    } while (0)

    const int ntiles = (t1 - t0 + TILE - 1) / TILE;
    PREF(t0, min(TILE, t1 - t0), buf0);

    for (int i = 0; i < ntiles; i++) {
        const int t      = t0 + i * TILE;
        const int nvalid = min(TILE, t1 - t);
        float4* const cur = (i & 1) ? buf1 : buf0;

        if (i + 1 < ntiles) {
            float4* const nxt = ((i + 1) & 1) ? buf1 : buf0;
            const int tn = t0 + (i + 1) * TILE;
            PREF(tn, min(TILE, t1 - tn), nxt);
            __pipeline_wait_prior(1);    // current tile's group done
        } else {
            __pipeline_wait_prior(0);
        }

        // ---- 8 partial dots from smem, pipelined warp reduce ----
        float d[TILE];
#pragma unroll
        for (int j = 0; j < TILE; j++) {
            if (j < nvalid) {
                const float4 v = cur[j * 256 + tid];
                d[j] = v.x * w.x + v.y * w.y + v.z * w.z + v.w * w.w;
            } else d[j] = 0.0f;
        }
#pragma unroll
        for (int o = 16; o > 0; o >>= 1) {
#pragma unroll
            for (int j = 0; j < TILE; j++)
                d[j] += __shfl_xor_sync(0xffffffffu, d[j], o);
        }
        if (lane == 0) {
#pragma unroll
            for (int j = 0; j < TILE; j++) s_part[wid][j] = d[j];
        }
        __syncthreads();

        // ---- warp 0 finishes 8 block-sums + exps ----
        if (wid == 0 && lane < TILE) {
            float s = 0.0f;
#pragma unroll
            for (int ww = 0; ww < 8; ww++) s += s_part[ww][lane];
            s_p[lane] = __expf(s + b);   // unshifted exp: |score| <~ 6
        }
        __syncthreads();

        // ---- accumulate (reread own column from smem) ----
#pragma unroll
        for (int j = 0; j < TILE; j++) {
            const int tt = t + j;
            if (j >= nvalid) break;
            if (tt >= nb) {              // rare segment boundary
                FLUSH();
                acc = make_float4(0.f, 0.f, 0.f, 0.f);  sump = 0.0f;
                do { seg++; nb = s_cu[seg + 1]; } while (tt >= nb);
            }
            const float p = s_p[j];
            const float4 v = cur[j * 256 + tid];
            sump += p;
            acc.x += p * v.x;  acc.y += p * v.y;
            acc.z += p * v.z;  acc.w += p * v.w;
        }
    }
    FLUSH();
#undef FLUSH
#undef PREF
}

// ---------------------------------------------------------------------------
// Norm kernel (unchanged, R5-proven): one block per segment; writes out, then
// re-zeroes scratch/sums so the next graph replay starts clean.
// ---------------------------------------------------------------------------
__global__ void norm_kernel(float* __restrict__ out) {
    const int s = blockIdx.x;
    const int i = s * D_MODEL + threadIdx.x;
    const float inv = 1.0f / g_seg_sum[s];
    out[i] = g_scratch[i] * inv;
    g_scratch[i] = 0.0f;
    __syncthreads();
    if (threadIdx.x == 0) g_seg_sum[s] = 0.0f;
}

// ---------------------------------------------------------------------------
extern "C" void kernel_launch(void* const* d_in, const int* in_sizes, int n_in,
                              void* d_out, int out_size) {
    const float* x  = (const float*)d_in[0];
    const int*   cu = (const int*)  d_in[1];
    const float* W  = (const float*)d_in[2];
    const float* b  = (const float*)d_in[3];
    float* out = (float*)d_out;

    const int T    = in_sizes[0] / D_MODEL;
    const int nseg = in_sizes[1] - 1;

    const int smem_bytes = 2 * TILE * 256 * (int)sizeof(float4);   // 64KB
    cudaFuncSetAttribute(pool_kernel,
                         cudaFuncAttributeMaxDynamicSharedMemorySize, smem_bytes);

    pool_kernel<<<NBLOCKS, NTHREADS, smem_bytes>>>(x, cu, W, b, T, nseg);
    norm_kernel<<<nseg, D_MODEL>>>(out);
}

// round 13
// speedup vs baseline: 1.4162x; 1.4162x over previous
#include <cuda_runtime.h>
#include <cuda_bf16.h>

#define D_MODEL 1024
#define MAX_SEGS 256
#define NTHREADS 256
#define NBLOCKS  1184        // 8 * 148
#define TILE 8

__device__ float g_seg_sum[MAX_SEGS];              // zero-init at load; norm re-zeroes
__device__ float g_scratch[MAX_SEGS * D_MODEL];    // zero-init at load; norm re-zeroes

// ---------------------------------------------------------------------------
// Main kernel: CTA-per-token-range, 8-token tiles.  (R5 shape, verbatim.)
// Thread tid owns dims [4*tid, 4*tid+4). 8 float4 loads in flight per thread;
// 2 __syncthreads per 8 tokens; 8 shfl-reduces pipelined.
// ---------------------------------------------------------------------------
__global__ __launch_bounds__(NTHREADS)
void pool_kernel(const float* __restrict__ x,
                 const int*   __restrict__ cu,
                 const float* __restrict__ Wp,
                 const float* __restrict__ bp,
                 int T, int nseg) {
    __shared__ float s_part[8][TILE];   // [warp][token]
    __shared__ float s_p[TILE];
    __shared__ int   s_cu[MAX_SEGS + 1];

    const int tid  = threadIdx.x;
    const int lane = tid & 31;
    const int wid  = tid >> 5;

    if (tid <= nseg) s_cu[tid] = cu[tid];

    const float4 w = *reinterpret_cast<const float4*>(Wp + tid * 4);
    const float  b = bp[0];

    const int per = (T + NBLOCKS - 1) / NBLOCKS;
    const int t0  = blockIdx.x * per;
    const int t1  = min(t0 + per, T);
    __syncthreads();
    if (t0 >= t1) return;

    int seg = 0;
    while (s_cu[seg + 1] <= t0) seg++;
    int nb = s_cu[seg + 1];

    float4 acc = make_float4(0.f, 0.f, 0.f, 0.f);
    float  sump = 0.0f;

    const float4* xv = reinterpret_cast<const float4*>(x);

#define FLUSH()                                                            \
    do {                                                                   \
        float* o = g_scratch + (size_t)seg * D_MODEL + tid * 4;            \
        atomicAdd(o + 0, acc.x);  atomicAdd(o + 1, acc.y);                 \
        atomicAdd(o + 2, acc.z);  atomicAdd(o + 3, acc.w);                 \
        if (tid == 0) atomicAdd(&g_seg_sum[seg], sump);                    \
    } while (0)

    for (int t = t0; t < t1; t += TILE) {
        const int nvalid = min(TILE, t1 - t);

        // ---- Phase 1: load 8 rows (8 independent LDG.128 per thread) ----
        float4 v[TILE];
#pragma unroll
        for (int j = 0; j < TILE; j++) {
            if (j < nvalid) v[j] = xv[(size_t)(t + j) * 256 + tid];
            else            v[j] = make_float4(0.f, 0.f, 0.f, 0.f);
        }

        // ---- Phase 2: 8 partial dots, pipelined warp reduce ----
        float d[TILE];
#pragma unroll
        for (int j = 0; j < TILE; j++)
            d[j] = v[j].x * w.x + v[j].y * w.y + v[j].z * w.z + v[j].w * w.w;
#pragma unroll
        for (int o = 16; o > 0; o >>= 1) {
#pragma unroll
            for (int j = 0; j < TILE; j++)
                d[j] += __shfl_xor_sync(0xffffffffu, d[j], o);
        }
        if (lane == 0) {
#pragma unroll
            for (int j = 0; j < TILE; j++) s_part[wid][j] = d[j];
        }
        __syncthreads();

        // ---- Phase 3: warp 0 finishes 8 block-sums + exps ----
        if (wid == 0 && lane < TILE) {
            float s = 0.0f;
#pragma unroll
            for (int ww = 0; ww < 8; ww++) s += s_part[ww][lane];
            s_p[lane] = __expf(s + b);   // unshifted exp: |score| <~ 6
        }
        __syncthreads();

        // ---- Phase 4: accumulate, with rare segment-boundary flushes ----
#pragma unroll
        for (int j = 0; j < TILE; j++) {
            const int tt = t + j;
            if (j >= nvalid) break;
            if (tt >= nb) {              // rare: 63 crossings / 16K tiles
                FLUSH();
                acc = make_float4(0.f, 0.f, 0.f, 0.f);  sump = 0.0f;
                do { seg++; nb = s_cu[seg + 1]; } while (tt >= nb);
            }
            const float p = s_p[j];
            sump += p;
            acc.x += p * v[j].x;  acc.y += p * v[j].y;
            acc.z += p * v[j].z;  acc.w += p * v[j].w;
        }
    }
    FLUSH();
#undef FLUSH
}

// ---------------------------------------------------------------------------
// Norm kernel: one block per segment, 256 threads, float4-vectorized.
// Writes out, then re-zeroes scratch/sums so the next graph replay starts
// clean (all readers of g_seg_sum[s] are in block s -> race-free).
// ---------------------------------------------------------------------------
__global__ void norm_kernel(float* __restrict__ out) {
    const int s   = blockIdx.x;
    const int tid = threadIdx.x;
    const float inv = 1.0f / g_seg_sum[s];

    float4* sc = reinterpret_cast<float4*>(g_scratch + (size_t)s * D_MODEL);
    float4* o  = reinterpret_cast<float4*>(out       + (size_t)s * D_MODEL);

    const float4 v = sc[tid];
    o[tid]  = make_float4(v.x * inv, v.y * inv, v.z * inv, v.w * inv);
    sc[tid] = make_float4(0.f, 0.f, 0.f, 0.f);
    __syncthreads();
    if (tid == 0) g_seg_sum[s] = 0.0f;
}

// ---------------------------------------------------------------------------
extern "C" void kernel_launch(void* const* d_in, const int* in_sizes, int n_in,
                              void* d_out, int out_size) {
    const float* x  = (const float*)d_in[0];
    const int*   cu = (const int*)  d_in[1];
    const float* W  = (const float*)d_in[2];
    const float* b  = (const float*)d_in[3];
    float* out = (float*)d_out;

    const int T    = in_sizes[0] / D_MODEL;
    const int nseg = in_sizes[1] - 1;

    pool_kernel<<<NBLOCKS, NTHREADS>>>(x, cu, W, b, T, nseg);
    norm_kernel<<<nseg, NTHREADS>>>(out);
}